// round 10
// baseline (speedup 1.0000x reference)
#include <cuda_runtime.h>
#include <cuda_fp16.h>
#include <cuda_bf16.h>
#include <cstddef>

#define NN 100000
#define EE 1600000
#define FULLM 0xffffffffu

// ---------------- scratch (device globals; no allocation) ----------------
__device__ __half2 g_h1h[(size_t)NN * 32];  // packed {h[c], h[c+32]} per node
__device__ float g_asrc1[NN * 4];
__device__ float g_adst1[NN * 4];
__device__ float2 g_p2[NN];                 // {h2, asrc2}
__device__ float g_adst2[NN];
// CSR (sorted-by-dst) structures — REAL edges only (self-loops analytic)
__device__ int g_cnt[NN];
__device__ int g_start[NN + 1];
__device__ int g_pos[NN];
__device__ int g_esrc[EE];
__device__ float4 g_ee[EE];                 // per-edge exp(leaky(alpha)) per head

// ---------------- K0: zero degree counters ----------------
__global__ void k_init_cnt() {
    int i = blockIdx.x * blockDim.x + threadIdx.x;
    if (i < NN) g_cnt[i] = 0;
}

// ---------------- K1: h1 = x @ W1 (fp16-packed out), plus attention dots ----------------
__global__ __launch_bounds__(256) void k_gemm1(const float* __restrict__ x,
                                               const float* __restrict__ W1,
                                               const float* __restrict__ att_s,
                                               const float* __restrict__ att_d) {
    __shared__ float Wsh[64 * 64];
    __shared__ float xsh[64 * 64];
    int t = threadIdx.x;
    int n0 = blockIdx.x * 64;

    for (int i = t; i < 4096; i += 256) Wsh[i] = W1[i];
    for (int i = t; i < 4096; i += 256) {
        int n = n0 + (i >> 6);
        xsh[i] = (n < NN) ? x[(size_t)n0 * 64 + i] : 0.f;
    }
    __syncthreads();

    int tx = t & 15, ty = t >> 4;
    int lane = t & 31;
    int j0 = tx * 4;
    float acc[4][4];
#pragma unroll
    for (int i = 0; i < 4; i++)
#pragma unroll
        for (int q = 0; q < 4; q++) acc[i][q] = 0.f;

#pragma unroll 4
    for (int k4 = 0; k4 < 64; k4 += 4) {
        float4 xv[4];
#pragma unroll
        for (int i = 0; i < 4; i++)
            xv[i] = *(const float4*)&xsh[(ty * 4 + i) * 64 + k4];
#pragma unroll
        for (int kk = 0; kk < 4; kk++) {
            float4 w = *(const float4*)&Wsh[(k4 + kk) * 64 + j0];
#pragma unroll
            for (int i = 0; i < 4; i++) {
                float xvk = ((const float*)&xv[i])[kk];
                acc[i][0] = fmaf(xvk, w.x, acc[i][0]);
                acc[i][1] = fmaf(xvk, w.y, acc[i][1]);
                acc[i][2] = fmaf(xvk, w.z, acc[i][2]);
                acc[i][3] = fmaf(xvk, w.w, acc[i][3]);
            }
        }
    }

    float4 as = *(const float4*)&att_s[j0];
    float4 ad = *(const float4*)&att_d[j0];
    int head = tx >> 2;

#pragma unroll
    for (int i = 0; i < 4; i++) {
        int n = n0 + ty * 4 + i;
        // pack fp16 pairs {c, c+32}: partner channels live in lane+8 (tx+8)
        float h0 = __shfl_sync(FULLM, acc[i][0], lane + 8);
        float h1v = __shfl_sync(FULLM, acc[i][1], lane + 8);
        float h2v = __shfl_sync(FULLM, acc[i][2], lane + 8);
        float h3v = __shfl_sync(FULLM, acc[i][3], lane + 8);
        if (tx < 8 && n < NN) {
            __half2 p0 = __floats2half2_rn(acc[i][0], h0);
            __half2 p1 = __floats2half2_rn(acc[i][1], h1v);
            __half2 p2 = __floats2half2_rn(acc[i][2], h2v);
            __half2 p3 = __floats2half2_rn(acc[i][3], h3v);
            uint4 u = make_uint4(*(unsigned*)&p0, *(unsigned*)&p1,
                                 *(unsigned*)&p2, *(unsigned*)&p3);
            *(uint4*)&g_h1h[(size_t)n * 32 + j0] = u;
        }
        float ps = acc[i][0] * as.x + acc[i][1] * as.y + acc[i][2] * as.z + acc[i][3] * as.w;
        float pd = acc[i][0] * ad.x + acc[i][1] * ad.y + acc[i][2] * ad.z + acc[i][3] * ad.w;
        ps += __shfl_xor_sync(FULLM, ps, 1);
        ps += __shfl_xor_sync(FULLM, ps, 2);
        pd += __shfl_xor_sync(FULLM, pd, 1);
        pd += __shfl_xor_sync(FULLM, pd, 2);
        if ((tx & 3) == 0 && n < NN) {
            g_asrc1[n * 4 + head] = ps;
            g_adst1[n * 4 + head] = pd;
        }
    }
}

// ---------------- K2: histogram of dst (4 edges/thread) ----------------
__global__ __launch_bounds__(256) void k_hist(const int* __restrict__ ei) {
    int t = blockIdx.x * 256 + threadIdx.x;
    if (t >= EE / 4) return;
    int4 d = ((const int4*)(ei + EE))[t];
    atomicAdd(&g_cnt[d.x], 1);
    atomicAdd(&g_cnt[d.y], 1);
    atomicAdd(&g_cnt[d.z], 1);
    atomicAdd(&g_cnt[d.w], 1);
}

// ---------------- K3: single-block exclusive scan over counts ----------------
__global__ __launch_bounds__(1024) void k_scan() {
    __shared__ int sh[1024];
    const int T = 1024, CH = (NN + T - 1) / T;  // 98
    int t = threadIdx.x;
    int base = t * CH;
    int local = 0;
    for (int i = 0; i < CH; i++) {
        int idx = base + i;
        if (idx < NN) local += g_cnt[idx];
    }
    sh[t] = local;
    __syncthreads();
    for (int off = 1; off < T; off <<= 1) {
        int v = (t >= off) ? sh[t - off] : 0;
        __syncthreads();
        sh[t] += v;
        __syncthreads();
    }
    int run = (t == 0) ? 0 : sh[t - 1];
    for (int i = 0; i < CH; i++) {
        int idx = base + i;
        if (idx < NN) {
            int c = g_cnt[idx];
            g_start[idx] = run;
            g_pos[idx] = run;
            run += c;
        }
    }
    if (t == T - 1) g_start[NN] = run;
}

// ---------------- K4: scatter src + per-edge exp vector into CSR slots ----------------
// Atomic round-trip (~320cyc) shadows the attention loads + expf (issue slack was 98%).
__global__ __launch_bounds__(256) void k_scatter(const int* __restrict__ ei) {
    int t = blockIdx.x * 256 + threadIdx.x;
    if (t >= EE / 4) return;
    int4 s4 = ((const int4*)ei)[t];
    int4 d4 = ((const int4*)(ei + EE))[t];
    int ss[4] = {s4.x, s4.y, s4.z, s4.w};
    int dd[4] = {d4.x, d4.y, d4.z, d4.w};
    int pp[4];
#pragma unroll
    for (int k = 0; k < 4; k++) pp[k] = atomicAdd(&g_pos[dd[k]], 1);
#pragma unroll
    for (int k = 0; k < 4; k++) {
        float4 as = *(const float4*)&g_asrc1[ss[k] * 4];
        float4 ad = *(const float4*)&g_adst1[dd[k] * 4];
        float a0 = as.x + ad.x; a0 = a0 > 0.f ? a0 : 0.2f * a0;
        float a1 = as.y + ad.y; a1 = a1 > 0.f ? a1 : 0.2f * a1;
        float a2 = as.z + ad.z; a2 = a2 > 0.f ? a2 : 0.2f * a2;
        float a3 = as.w + ad.w; a3 = a3 > 0.f ? a3 : 0.2f * a3;
        float4 e = make_float4(__expf(a0), __expf(a1), __expf(a2), __expf(a3));
        g_esrc[pp[k]] = ss[k];
        g_ee[pp[k]] = e;
    }
}

// ---------------- K5: layer-1 gather-reduce + normalize + bias + ELU + GEMM2 ----------------
// Warp per dst node; lane holds packed channels (lane, lane+32). Self-loop analytic.
__global__ __launch_bounds__(256) void k_gather1(const float* __restrict__ b1,
                                                 const float* __restrict__ W2,
                                                 const float* __restrict__ as2,
                                                 const float* __restrict__ ad2) {
    __shared__ int    s_src[8][32];
    __shared__ float2 s_ee[8][2][32];
    int wIn = threadIdx.x >> 5;
    int lane = threadIdx.x & 31;
    int n = blockIdx.x * 8 + wIn;
    if (n >= NN) return;

    int s = g_start[n], eend = g_start[n + 1];

    // self-loop attention (same value in all lanes; cheap)
    float4 asn = *(const float4*)&g_asrc1[n * 4];
    float4 adn = *(const float4*)&g_adst1[n * 4];
    float sa0 = asn.x + adn.x; sa0 = sa0 > 0.f ? sa0 : 0.2f * sa0;
    float sa1 = asn.y + adn.y; sa1 = sa1 > 0.f ? sa1 : 0.2f * sa1;
    float sa2 = asn.z + adn.z; sa2 = sa2 > 0.f ? sa2 : 0.2f * sa2;
    float sa3 = asn.w + adn.w; sa3 = sa3 > 0.f ? sa3 : 0.2f * sa3;
    float se0 = __expf(sa0), se1 = __expf(sa1), se2 = __expf(sa2), se3 = __expf(sa3);
    float seA = (lane < 16) ? se0 : se1;
    float seB = (lane < 16) ? se2 : se3;

    float2 fself = __half22float2(g_h1h[(size_t)n * 32 + lane]);
    float acc0 = fself.x * seA;
    float acc1 = fself.y * seB;
    float d0 = 0.f, d1 = 0.f, d2 = 0.f, d3 = 0.f;

    const float2* ep = s_ee[wIn][lane >= 16 ? 1 : 0];

    for (int base = s; base < eend; base += 32) {
        int j = base + lane;
        bool v = (j < eend);
        int sj = v ? g_esrc[j] : 0;
        float4 ev = v ? g_ee[j] : make_float4(0.f, 0.f, 0.f, 0.f);
        d0 += ev.x; d1 += ev.y; d2 += ev.z; d3 += ev.w;
        s_src[wIn][lane] = sj;
        s_ee[wIn][0][lane] = make_float2(ev.x, ev.z);   // heads (0,2)
        s_ee[wIn][1][lane] = make_float2(ev.y, ev.w);   // heads (1,3)
        __syncwarp();

        int cnt = eend - base; if (cnt > 32) cnt = 32;
        int q = 0;
        for (; q + 8 <= cnt; q += 8) {
            unsigned hv[8];
#pragma unroll
            for (int u = 0; u < 8; u++) {
                int sq = s_src[wIn][q + u];
                hv[u] = *(const unsigned*)&g_h1h[(size_t)sq * 32 + lane];
            }
#pragma unroll
            for (int u = 0; u < 8; u++) {
                float2 f = __half22float2(*(__half2*)&hv[u]);
                float2 eq = ep[q + u];
                acc0 = fmaf(f.x, eq.x, acc0);
                acc1 = fmaf(f.y, eq.y, acc1);
            }
        }
        for (; q < cnt; q++) {
            int sq = s_src[wIn][q];
            float2 f = __half22float2(g_h1h[(size_t)sq * 32 + lane]);
            float2 eq = ep[q];
            acc0 = fmaf(f.x, eq.x, acc0);
            acc1 = fmaf(f.y, eq.y, acc1);
        }
        __syncwarp();
    }

#pragma unroll
    for (int off = 16; off; off >>= 1) {
        d0 += __shfl_xor_sync(FULLM, d0, off);
        d1 += __shfl_xor_sync(FULLM, d1, off);
        d2 += __shfl_xor_sync(FULLM, d2, off);
        d3 += __shfl_xor_sync(FULLM, d3, off);
    }
    float dA = ((lane < 16) ? d0 : d1) + seA;
    float dB = ((lane < 16) ? d2 : d3) + seB;

    float o0 = acc0 / (dA + 1e-16f) + b1[lane];
    float o1 = acc1 / (dB + 1e-16f) + b1[lane + 32];
    o0 = o0 > 0.f ? o0 : expm1f(o0);   // ELU
    o1 = o1 > 0.f ? o1 : expm1f(o1);

    float p = o0 * W2[lane] + o1 * W2[lane + 32];
#pragma unroll
    for (int off = 16; off; off >>= 1) p += __shfl_xor_sync(FULLM, p, off);

    if (lane == 0) {
        g_p2[n] = make_float2(p, p * as2[0]);   // {h2, asrc2}
        g_adst2[n] = p * ad2[0];
    }
}

// ---------------- K6: layer-2 gather + output (self-loop analytic) ----------------
__global__ __launch_bounds__(256) void k_gather2(float* __restrict__ out,
                                                 const float* __restrict__ b2) {
    int n = (blockIdx.x * 256 + threadIdx.x) >> 5;
    int lane = threadIdx.x & 31;
    if (n >= NN) return;

    int s = g_start[n], eend = g_start[n + 1];
    float adn = g_adst2[n];
    float2 pn = g_p2[n];
    float num = 0.f, den = 0.f;
    for (int j = s + lane; j < eend; j += 32) {
        int src = g_esrc[j];
        float2 hs = g_p2[src];
        float a = hs.y + adn;
        a = a > 0.f ? a : 0.2f * a;
        float e = __expf(a);
        den += e;
        num = fmaf(hs.x, e, num);
    }
#pragma unroll
    for (int off = 16; off; off >>= 1) {
        num += __shfl_xor_sync(FULLM, num, off);
        den += __shfl_xor_sync(FULLM, den, off);
    }
    if (lane == 0) {
        float a = pn.y + adn;
        a = a > 0.f ? a : 0.2f * a;
        float e = __expf(a);
        den += e;
        num = fmaf(pn.x, e, num);
        out[n] = num / (den + 1e-16f) + b2[0];
    }
}

// ---------------- launch ----------------
extern "C" void kernel_launch(void* const* d_in, const int* in_sizes, int n_in,
                              void* d_out, int out_size) {
    const float* x   = (const float*)d_in[0];
    const int*   ei  = (const int*)d_in[1];
    const float* W1  = (const float*)d_in[2];
    const float* as1 = (const float*)d_in[3];
    const float* ad1 = (const float*)d_in[4];
    const float* b1  = (const float*)d_in[5];
    const float* W2  = (const float*)d_in[6];
    const float* as2 = (const float*)d_in[7];
    const float* ad2 = (const float*)d_in[8];
    const float* b2  = (const float*)d_in[9];
    float* out = (float*)d_out;

    k_init_cnt<<<(NN + 255) / 256, 256>>>();
    k_gemm1   <<<(NN + 63) / 64, 256>>>(x, W1, as1, ad1);
    k_hist    <<<(EE / 4 + 255) / 256, 256>>>(ei);
    k_scan    <<<1, 1024>>>();
    k_scatter <<<(EE / 4 + 255) / 256, 256>>>(ei);
    k_gather1 <<<(NN + 7) / 8, 256>>>(b1, W2, as2, ad2);
    k_gather2 <<<(NN * 32 + 255) / 256, 256>>>(out, b2);
}

// round 13
// speedup vs baseline: 1.8240x; 1.8240x over previous
#include <cuda_runtime.h>
#include <cuda_fp16.h>
#include <cuda_bf16.h>
#include <cstddef>

#define NN 100000
#define EE 1600000
#define FULLM 0xffffffffu
#define NBLK ((NN + 255) / 256)   // 391 scan blocks

// ---------------- scratch (device globals; no allocation) ----------------
__device__ __half2 g_h1h[(size_t)NN * 32];  // packed {h[c], h[c+32]} per node
__device__ float g_asrc1[NN * 4];
__device__ float g_adst1[NN * 4];
__device__ float2 g_p2[NN];                 // {h2, asrc2}
__device__ float g_adst2[NN];
// CSR (sorted-by-dst) structures — REAL edges only (self-loops analytic)
__device__ int g_cnt[NN];
__device__ int g_bsum[NBLK];
__device__ int g_boff[NBLK];
__device__ int g_start[NN + 1];
__device__ int g_pos[NN];
__device__ int g_esrc[EE];
__device__ float4 g_ee[EE];                 // per-edge exp(leaky(alpha)) per head

// ---------------- K0: zero degree counters ----------------
__global__ void k_init_cnt() {
    int i = blockIdx.x * blockDim.x + threadIdx.x;
    if (i < NN) g_cnt[i] = 0;
}

// ---------------- K1: h1 = x @ W1 (fp16-packed out), plus attention dots ----------------
__global__ __launch_bounds__(256) void k_gemm1(const float* __restrict__ x,
                                               const float* __restrict__ W1,
                                               const float* __restrict__ att_s,
                                               const float* __restrict__ att_d) {
    __shared__ float Wsh[64 * 64];
    __shared__ float xsh[64 * 64];
    int t = threadIdx.x;
    int n0 = blockIdx.x * 64;

    for (int i = t; i < 4096; i += 256) Wsh[i] = W1[i];
    for (int i = t; i < 4096; i += 256) {
        int n = n0 + (i >> 6);
        xsh[i] = (n < NN) ? x[(size_t)n0 * 64 + i] : 0.f;
    }
    __syncthreads();

    int tx = t & 15, ty = t >> 4;
    int lane = t & 31;
    int j0 = tx * 4;
    float acc[4][4];
#pragma unroll
    for (int i = 0; i < 4; i++)
#pragma unroll
        for (int q = 0; q < 4; q++) acc[i][q] = 0.f;

#pragma unroll 4
    for (int k4 = 0; k4 < 64; k4 += 4) {
        float4 xv[4];
#pragma unroll
        for (int i = 0; i < 4; i++)
            xv[i] = *(const float4*)&xsh[(ty * 4 + i) * 64 + k4];
#pragma unroll
        for (int kk = 0; kk < 4; kk++) {
            float4 w = *(const float4*)&Wsh[(k4 + kk) * 64 + j0];
#pragma unroll
            for (int i = 0; i < 4; i++) {
                float xvk = ((const float*)&xv[i])[kk];
                acc[i][0] = fmaf(xvk, w.x, acc[i][0]);
                acc[i][1] = fmaf(xvk, w.y, acc[i][1]);
                acc[i][2] = fmaf(xvk, w.z, acc[i][2]);
                acc[i][3] = fmaf(xvk, w.w, acc[i][3]);
            }
        }
    }

    float4 as = *(const float4*)&att_s[j0];
    float4 ad = *(const float4*)&att_d[j0];
    int head = tx >> 2;

#pragma unroll
    for (int i = 0; i < 4; i++) {
        int n = n0 + ty * 4 + i;
        // pack fp16 pairs {c, c+32}: partner channels live in lane+8 (tx+8)
        float h0 = __shfl_sync(FULLM, acc[i][0], lane + 8);
        float h1v = __shfl_sync(FULLM, acc[i][1], lane + 8);
        float h2v = __shfl_sync(FULLM, acc[i][2], lane + 8);
        float h3v = __shfl_sync(FULLM, acc[i][3], lane + 8);
        if (tx < 8 && n < NN) {
            __half2 p0 = __floats2half2_rn(acc[i][0], h0);
            __half2 p1 = __floats2half2_rn(acc[i][1], h1v);
            __half2 p2 = __floats2half2_rn(acc[i][2], h2v);
            __half2 p3 = __floats2half2_rn(acc[i][3], h3v);
            uint4 u = make_uint4(*(unsigned*)&p0, *(unsigned*)&p1,
                                 *(unsigned*)&p2, *(unsigned*)&p3);
            *(uint4*)&g_h1h[(size_t)n * 32 + j0] = u;
        }
        float ps = acc[i][0] * as.x + acc[i][1] * as.y + acc[i][2] * as.z + acc[i][3] * as.w;
        float pd = acc[i][0] * ad.x + acc[i][1] * ad.y + acc[i][2] * ad.z + acc[i][3] * ad.w;
        ps += __shfl_xor_sync(FULLM, ps, 1);
        ps += __shfl_xor_sync(FULLM, ps, 2);
        pd += __shfl_xor_sync(FULLM, pd, 1);
        pd += __shfl_xor_sync(FULLM, pd, 2);
        if ((tx & 3) == 0 && n < NN) {
            g_asrc1[n * 4 + head] = ps;
            g_adst1[n * 4 + head] = pd;
        }
    }
}

// ---------------- K2: histogram of dst (4 edges/thread) ----------------
__global__ __launch_bounds__(256) void k_hist(const int* __restrict__ ei) {
    int t = blockIdx.x * 256 + threadIdx.x;
    if (t >= EE / 4) return;
    int4 d = ((const int4*)(ei + EE))[t];
    atomicAdd(&g_cnt[d.x], 1);
    atomicAdd(&g_cnt[d.y], 1);
    atomicAdd(&g_cnt[d.z], 1);
    atomicAdd(&g_cnt[d.w], 1);
}

// ---------------- K3a: per-block sums of counts ----------------
__global__ __launch_bounds__(256) void k_blocksum() {
    int idx = blockIdx.x * 256 + threadIdx.x;
    int c = (idx < NN) ? g_cnt[idx] : 0;
#pragma unroll
    for (int off = 16; off; off >>= 1) c += __shfl_xor_sync(FULLM, c, off);
    __shared__ int wsum[8];
    if ((threadIdx.x & 31) == 0) wsum[threadIdx.x >> 5] = c;
    __syncthreads();
    if (threadIdx.x < 8) {
        int v = wsum[threadIdx.x];
#pragma unroll
        for (int off = 4; off; off >>= 1) v += __shfl_xor_sync(0xffu, v, off);
        if (threadIdx.x == 0) g_bsum[blockIdx.x] = v;
    }
}

// ---------------- K3b: single-block exclusive scan of 391 block sums ----------------
__global__ __launch_bounds__(512) void k_scanbsum() {
    __shared__ int sh[512];
    int t = threadIdx.x;
    sh[t] = (t < NBLK) ? g_bsum[t] : 0;
    __syncthreads();
    for (int off = 1; off < 512; off <<= 1) {
        int v = (t >= off) ? sh[t - off] : 0;
        __syncthreads();
        sh[t] += v;
        __syncthreads();
    }
    if (t < NBLK) g_boff[t] = (t == 0) ? 0 : sh[t - 1];
}

// ---------------- K3c: per-block exclusive scan + offset -> g_start/g_pos ----------------
__global__ __launch_bounds__(256) void k_scanfinal() {
    int idx = blockIdx.x * 256 + threadIdx.x;
    int lane = threadIdx.x & 31;
    int w = threadIdx.x >> 5;
    int c = (idx < NN) ? g_cnt[idx] : 0;
    // inclusive warp scan
    int v = c;
#pragma unroll
    for (int off = 1; off < 32; off <<= 1) {
        int u = __shfl_up_sync(FULLM, v, off);
        if (lane >= off) v += u;
    }
    __shared__ int wtot[8];
    if (lane == 31) wtot[w] = v;
    __syncthreads();
    int wpre = 0;
    if (threadIdx.x < 8) {
        int a = wtot[threadIdx.x];
        int p = a;
#pragma unroll
        for (int off = 1; off < 8; off <<= 1) {
            int u = __shfl_up_sync(0xffu, p, off);
            if (threadIdx.x >= off) p += u;
        }
        wtot[threadIdx.x] = p - a;   // exclusive
    }
    __syncthreads();
    wpre = wtot[w];
    int excl = g_boff[blockIdx.x] + wpre + (v - c);
    if (idx < NN) { g_start[idx] = excl; g_pos[idx] = excl; }
    if (idx == 0) g_start[NN] = EE;
}

// ---------------- K4: scatter src + per-edge exp vector into CSR slots ----------------
__global__ __launch_bounds__(256) void k_scatter(const int* __restrict__ ei) {
    int t = blockIdx.x * 256 + threadIdx.x;
    if (t >= EE / 4) return;
    int4 s4 = ((const int4*)ei)[t];
    int4 d4 = ((const int4*)(ei + EE))[t];
    int ss[4] = {s4.x, s4.y, s4.z, s4.w};
    int dd[4] = {d4.x, d4.y, d4.z, d4.w};
    int pp[4];
#pragma unroll
    for (int k = 0; k < 4; k++) pp[k] = atomicAdd(&g_pos[dd[k]], 1);
#pragma unroll
    for (int k = 0; k < 4; k++) {
        float4 as = *(const float4*)&g_asrc1[ss[k] * 4];
        float4 ad = *(const float4*)&g_adst1[dd[k] * 4];
        float a0 = as.x + ad.x; a0 = a0 > 0.f ? a0 : 0.2f * a0;
        float a1 = as.y + ad.y; a1 = a1 > 0.f ? a1 : 0.2f * a1;
        float a2 = as.z + ad.z; a2 = a2 > 0.f ? a2 : 0.2f * a2;
        float a3 = as.w + ad.w; a3 = a3 > 0.f ? a3 : 0.2f * a3;
        float4 e = make_float4(__expf(a0), __expf(a1), __expf(a2), __expf(a3));
        g_esrc[pp[k]] = ss[k];
        g_ee[pp[k]] = e;
    }
}

// ---------------- K5: layer-1 gather-reduce + normalize + bias + ELU + GEMM2 ----------------
__global__ __launch_bounds__(256) void k_gather1(const float* __restrict__ b1,
                                                 const float* __restrict__ W2,
                                                 const float* __restrict__ as2,
                                                 const float* __restrict__ ad2) {
    __shared__ int    s_src[8][32];
    __shared__ float2 s_ee[8][2][32];
    int wIn = threadIdx.x >> 5;
    int lane = threadIdx.x & 31;
    int n = blockIdx.x * 8 + wIn;
    if (n >= NN) return;

    int s = g_start[n], eend = g_start[n + 1];

    // self-loop attention (analytic)
    float4 asn = *(const float4*)&g_asrc1[n * 4];
    float4 adn = *(const float4*)&g_adst1[n * 4];
    float sa0 = asn.x + adn.x; sa0 = sa0 > 0.f ? sa0 : 0.2f * sa0;
    float sa1 = asn.y + adn.y; sa1 = sa1 > 0.f ? sa1 : 0.2f * sa1;
    float sa2 = asn.z + adn.z; sa2 = sa2 > 0.f ? sa2 : 0.2f * sa2;
    float sa3 = asn.w + adn.w; sa3 = sa3 > 0.f ? sa3 : 0.2f * sa3;
    float se0 = __expf(sa0), se1 = __expf(sa1), se2 = __expf(sa2), se3 = __expf(sa3);
    float seA = (lane < 16) ? se0 : se1;
    float seB = (lane < 16) ? se2 : se3;

    float2 fself = __half22float2(g_h1h[(size_t)n * 32 + lane]);
    float acc0 = fself.x * seA;
    float acc1 = fself.y * seB;
    float d0 = 0.f, d1 = 0.f, d2 = 0.f, d3 = 0.f;

    const float2* ep = s_ee[wIn][lane >= 16 ? 1 : 0];

    for (int base = s; base < eend; base += 32) {
        int j = base + lane;
        bool v = (j < eend);
        int sj = v ? g_esrc[j] : 0;
        float4 ev = v ? g_ee[j] : make_float4(0.f, 0.f, 0.f, 0.f);
        d0 += ev.x; d1 += ev.y; d2 += ev.z; d3 += ev.w;
        s_src[wIn][lane] = sj;
        s_ee[wIn][0][lane] = make_float2(ev.x, ev.z);   // heads (0,2)
        s_ee[wIn][1][lane] = make_float2(ev.y, ev.w);   // heads (1,3)
        __syncwarp();

        int cnt = eend - base; if (cnt > 32) cnt = 32;
        int q = 0;
        for (; q + 8 <= cnt; q += 8) {
            unsigned hv[8];
#pragma unroll
            for (int u = 0; u < 8; u++) {
                int sq = s_src[wIn][q + u];
                hv[u] = *(const unsigned*)&g_h1h[(size_t)sq * 32 + lane];
            }
#pragma unroll
            for (int u = 0; u < 8; u++) {
                float2 f = __half22float2(*(__half2*)&hv[u]);
                float2 eq = ep[q + u];
                acc0 = fmaf(f.x, eq.x, acc0);
                acc1 = fmaf(f.y, eq.y, acc1);
            }
        }
        for (; q < cnt; q++) {
            int sq = s_src[wIn][q];
            float2 f = __half22float2(g_h1h[(size_t)sq * 32 + lane]);
            float2 eq = ep[q];
            acc0 = fmaf(f.x, eq.x, acc0);
            acc1 = fmaf(f.y, eq.y, acc1);
        }
        __syncwarp();
    }

#pragma unroll
    for (int off = 16; off; off >>= 1) {
        d0 += __shfl_xor_sync(FULLM, d0, off);
        d1 += __shfl_xor_sync(FULLM, d1, off);
        d2 += __shfl_xor_sync(FULLM, d2, off);
        d3 += __shfl_xor_sync(FULLM, d3, off);
    }
    float dA = ((lane < 16) ? d0 : d1) + seA;
    float dB = ((lane < 16) ? d2 : d3) + seB;

    float o0 = acc0 / (dA + 1e-16f) + b1[lane];
    float o1 = acc1 / (dB + 1e-16f) + b1[lane + 32];
    o0 = o0 > 0.f ? o0 : expm1f(o0);   // ELU
    o1 = o1 > 0.f ? o1 : expm1f(o1);

    float p = o0 * W2[lane] + o1 * W2[lane + 32];
#pragma unroll
    for (int off = 16; off; off >>= 1) p += __shfl_xor_sync(FULLM, p, off);

    if (lane == 0) {
        g_p2[n] = make_float2(p, p * as2[0]);   // {h2, asrc2}
        g_adst2[n] = p * ad2[0];
    }
}

// ---------------- K6: layer-2 gather + output (self-loop analytic) ----------------
__global__ __launch_bounds__(256) void k_gather2(float* __restrict__ out,
                                                 const float* __restrict__ b2) {
    int n = (blockIdx.x * 256 + threadIdx.x) >> 5;
    int lane = threadIdx.x & 31;
    if (n >= NN) return;

    int s = g_start[n], eend = g_start[n + 1];
    float adn = g_adst2[n];
    float2 pn = g_p2[n];
    float num = 0.f, den = 0.f;
    for (int j = s + lane; j < eend; j += 32) {
        int src = g_esrc[j];
        float2 hs = g_p2[src];
        float a = hs.y + adn;
        a = a > 0.f ? a : 0.2f * a;
        float e = __expf(a);
        den += e;
        num = fmaf(hs.x, e, num);
    }
#pragma unroll
    for (int off = 16; off; off >>= 1) {
        num += __shfl_xor_sync(FULLM, num, off);
        den += __shfl_xor_sync(FULLM, den, off);
    }
    if (lane == 0) {
        float a = pn.y + adn;
        a = a > 0.f ? a : 0.2f * a;
        float e = __expf(a);
        den += e;
        num = fmaf(pn.x, e, num);
        out[n] = num / (den + 1e-16f) + b2[0];
    }
}

// ---------------- launch ----------------
extern "C" void kernel_launch(void* const* d_in, const int* in_sizes, int n_in,
                              void* d_out, int out_size) {
    const float* x   = (const float*)d_in[0];
    const int*   ei  = (const int*)d_in[1];
    const float* W1  = (const float*)d_in[2];
    const float* as1 = (const float*)d_in[3];
    const float* ad1 = (const float*)d_in[4];
    const float* b1  = (const float*)d_in[5];
    const float* W2  = (const float*)d_in[6];
    const float* as2 = (const float*)d_in[7];
    const float* ad2 = (const float*)d_in[8];
    const float* b2  = (const float*)d_in[9];
    float* out = (float*)d_out;

    k_init_cnt<<<NBLK, 256>>>();
    k_gemm1   <<<(NN + 63) / 64, 256>>>(x, W1, as1, ad1);
    k_hist    <<<(EE / 4 + 255) / 256, 256>>>(ei);
    k_blocksum<<<NBLK, 256>>>();
    k_scanbsum<<<1, 512>>>();
    k_scanfinal<<<NBLK, 256>>>();
    k_scatter <<<(EE / 4 + 255) / 256, 256>>>(ei);
    k_gather1 <<<(NN + 7) / 8, 256>>>(b1, W2, as2, ad2);
    k_gather2 <<<(NN * 32 + 255) / 256, 256>>>(out, b2);
}

// round 15
// speedup vs baseline: 1.8507x; 1.0146x over previous
#include <cuda_runtime.h>
#include <cuda_fp16.h>
#include <cuda_bf16.h>
#include <cstddef>

#define NN 100000
#define EE 1600000
#define FULLM 0xffffffffu
#define NBLK ((NN + 255) / 256)          // 391 scan blocks
#define GEMM_BLOCKS ((NN + 63) / 64)     // 1563
#define HIST_BLOCKS ((EE / 4 + 255) / 256) // 1563

// ---------------- scratch (device globals; no allocation) ----------------
__device__ __half2 g_h1h[(size_t)NN * 32];  // packed {h[c], h[c+32]} per node
__device__ float g_asrc1[NN * 4];
__device__ float g_adst1[NN * 4];
__device__ float2 g_p2[NN];                 // {h2, asrc2}
__device__ float g_adst2[NN];
// CSR (sorted-by-dst) — REAL edges only (self-loops analytic)
__device__ int g_cnt[NN];                   // zeroed by k_scatter of the PREVIOUS run (static 0 first)
__device__ int g_start[NN + 1];
__device__ int g_pos[NN];
__device__ int g_esrc[EE];
__device__ float4 g_ee[EE];                 // per-edge exp(leaky(alpha)) per head
// decoupled-lookback scan state (flags zeroed by gemm_hist each run)
__device__ int g_part[NBLK];
__device__ int g_incl[NBLK];
__device__ int g_flag[NBLK];

// ================= K1: fused [h1 = x @ W1 + attention dots] | [dst histogram] =================
__global__ __launch_bounds__(256) void k_gemm_hist(const float* __restrict__ x,
                                                   const float* __restrict__ W1,
                                                   const float* __restrict__ att_s,
                                                   const float* __restrict__ att_d,
                                                   const int* __restrict__ ei) {
    if (blockIdx.x >= GEMM_BLOCKS) {
        // ---- histogram branch ----
        int hb = blockIdx.x - GEMM_BLOCKS;
        int gid = hb * 256 + threadIdx.x;
        if (gid < NBLK) g_flag[gid] = 0;          // reset lookback flags for k_scan_lb
        if (gid < EE / 4) {
            int4 d = ((const int4*)(ei + EE))[gid];
            atomicAdd(&g_cnt[d.x], 1);
            atomicAdd(&g_cnt[d.y], 1);
            atomicAdd(&g_cnt[d.z], 1);
            atomicAdd(&g_cnt[d.w], 1);
        }
        return;
    }
    // ---- GEMM branch ----
    __shared__ float Wsh[64 * 64];
    __shared__ float xsh[64 * 64];
    int t = threadIdx.x;
    int n0 = blockIdx.x * 64;

    for (int i = t; i < 4096; i += 256) Wsh[i] = W1[i];
    for (int i = t; i < 4096; i += 256) {
        int n = n0 + (i >> 6);
        xsh[i] = (n < NN) ? x[(size_t)n0 * 64 + i] : 0.f;
    }
    __syncthreads();

    int tx = t & 15, ty = t >> 4;
    int lane = t & 31;
    int j0 = tx * 4;
    float acc[4][4];
#pragma unroll
    for (int i = 0; i < 4; i++)
#pragma unroll
        for (int q = 0; q < 4; q++) acc[i][q] = 0.f;

#pragma unroll 4
    for (int k4 = 0; k4 < 64; k4 += 4) {
        float4 xv[4];
#pragma unroll
        for (int i = 0; i < 4; i++)
            xv[i] = *(const float4*)&xsh[(ty * 4 + i) * 64 + k4];
#pragma unroll
        for (int kk = 0; kk < 4; kk++) {
            float4 w = *(const float4*)&Wsh[(k4 + kk) * 64 + j0];
#pragma unroll
            for (int i = 0; i < 4; i++) {
                float xvk = ((const float*)&xv[i])[kk];
                acc[i][0] = fmaf(xvk, w.x, acc[i][0]);
                acc[i][1] = fmaf(xvk, w.y, acc[i][1]);
                acc[i][2] = fmaf(xvk, w.z, acc[i][2]);
                acc[i][3] = fmaf(xvk, w.w, acc[i][3]);
            }
        }
    }

    float4 as = *(const float4*)&att_s[j0];
    float4 ad = *(const float4*)&att_d[j0];
    int head = tx >> 2;

#pragma unroll
    for (int i = 0; i < 4; i++) {
        int n = n0 + ty * 4 + i;
        float h0 = __shfl_sync(FULLM, acc[i][0], lane + 8);
        float h1v = __shfl_sync(FULLM, acc[i][1], lane + 8);
        float h2v = __shfl_sync(FULLM, acc[i][2], lane + 8);
        float h3v = __shfl_sync(FULLM, acc[i][3], lane + 8);
        if (tx < 8 && n < NN) {
            __half2 p0 = __floats2half2_rn(acc[i][0], h0);
            __half2 p1 = __floats2half2_rn(acc[i][1], h1v);
            __half2 p2 = __floats2half2_rn(acc[i][2], h2v);
            __half2 p3 = __floats2half2_rn(acc[i][3], h3v);
            uint4 u = make_uint4(*(unsigned*)&p0, *(unsigned*)&p1,
                                 *(unsigned*)&p2, *(unsigned*)&p3);
            *(uint4*)&g_h1h[(size_t)n * 32 + j0] = u;
        }
        float ps = acc[i][0] * as.x + acc[i][1] * as.y + acc[i][2] * as.z + acc[i][3] * as.w;
        float pd = acc[i][0] * ad.x + acc[i][1] * ad.y + acc[i][2] * ad.z + acc[i][3] * ad.w;
        ps += __shfl_xor_sync(FULLM, ps, 1);
        ps += __shfl_xor_sync(FULLM, ps, 2);
        pd += __shfl_xor_sync(FULLM, pd, 1);
        pd += __shfl_xor_sync(FULLM, pd, 2);
        if ((tx & 3) == 0 && n < NN) {
            g_asrc1[n * 4 + head] = ps;
            g_adst1[n * 4 + head] = pd;
        }
    }
}

// ================= K2: single-pass scan with warp-parallel decoupled lookback =================
__global__ __launch_bounds__(256) void k_scan_lb() {
    int b = blockIdx.x;
    int idx = b * 256 + threadIdx.x;
    int lane = threadIdx.x & 31;
    int w = threadIdx.x >> 5;
    int c = (idx < NN) ? g_cnt[idx] : 0;

    // inclusive warp scan of c
    int v = c;
#pragma unroll
    for (int off = 1; off < 32; off <<= 1) {
        int u = __shfl_up_sync(FULLM, v, off);
        if (lane >= off) v += u;
    }
    __shared__ int wtot[8];
    __shared__ int s_btot;
    __shared__ int s_off;
    if (lane == 31) wtot[w] = v;
    __syncthreads();
    if (threadIdx.x < 8) {
        int a = wtot[threadIdx.x];
        int p = a;
#pragma unroll
        for (int off = 1; off < 8; off <<= 1) {
            int u = __shfl_up_sync(0xffu, p, off);
            if (threadIdx.x >= off) p += u;
        }
        if (threadIdx.x == 7) s_btot = p;     // block total
        wtot[threadIdx.x] = p - a;            // exclusive warp prefix
    }
    __syncthreads();
    int btot = s_btot;

    // publish partial, lookback (warp 0), publish inclusive
    if (w == 0) {
        if (lane == 0 && b > 0) {
            g_part[b] = btot;
            __threadfence();
            atomicExch(&g_flag[b], 1);
        }
        int offset = 0;
        if (b > 0) {
            int i = b - 1;
            volatile int* vf = g_flag;
            volatile int* vp = g_part;
            volatile int* vi = g_incl;
            for (;;) {
                int id = i - lane;
                int f = 2, val = 0;
                if (id >= 0) {
                    f = vf[id];
                    val = (f == 2) ? vi[id] : ((f == 1) ? vp[id] : 0);
                }
                unsigned notready = __ballot_sync(FULLM, id >= 0 && f == 0);
                if (notready) continue;
                unsigned inclmask = __ballot_sync(FULLM, id < 0 || f == 2);
                int stop = inclmask ? (__ffs(inclmask) - 1) : 32;
                int contrib = ((lane < stop) || (lane == stop && id >= 0)) ? val : 0;
#pragma unroll
                for (int off = 16; off; off >>= 1) contrib += __shfl_xor_sync(FULLM, contrib, off);
                offset += contrib;
                if (stop < 32) break;
                i -= 32;
            }
        }
        if (lane == 0) {
            g_incl[b] = offset + btot;
            __threadfence();
            atomicExch(&g_flag[b], 2);
            s_off = offset;
        }
    }
    __syncthreads();
    int excl = s_off + wtot[w] + (v - c);
    if (idx < NN) { g_start[idx] = excl; g_pos[idx] = excl; }
    if (idx == 0) g_start[NN] = EE;
}

// ================= K3: scatter src + per-edge exp vector; re-zero g_cnt for next run =================
__global__ __launch_bounds__(256) void k_scatter(const int* __restrict__ ei) {
    int t = blockIdx.x * 256 + threadIdx.x;
    if (t >= EE / 4) return;
    if (t < NN) g_cnt[t] = 0;    // g_cnt is dead after the scan; prep next graph replay
    int4 s4 = ((const int4*)ei)[t];
    int4 d4 = ((const int4*)(ei + EE))[t];
    int ss[4] = {s4.x, s4.y, s4.z, s4.w};
    int dd[4] = {d4.x, d4.y, d4.z, d4.w};
    int pp[4];
#pragma unroll
    for (int k = 0; k < 4; k++) pp[k] = atomicAdd(&g_pos[dd[k]], 1);
#pragma unroll
    for (int k = 0; k < 4; k++) {
        float4 as = *(const float4*)&g_asrc1[ss[k] * 4];
        float4 ad = *(const float4*)&g_adst1[dd[k] * 4];
        float a0 = as.x + ad.x; a0 = a0 > 0.f ? a0 : 0.2f * a0;
        float a1 = as.y + ad.y; a1 = a1 > 0.f ? a1 : 0.2f * a1;
        float a2 = as.z + ad.z; a2 = a2 > 0.f ? a2 : 0.2f * a2;
        float a3 = as.w + ad.w; a3 = a3 > 0.f ? a3 : 0.2f * a3;
        float4 e = make_float4(__expf(a0), __expf(a1), __expf(a2), __expf(a3));
        g_esrc[pp[k]] = ss[k];
        g_ee[pp[k]] = e;
    }
}

// ================= K4: layer-1 gather-reduce + normalize + bias + ELU + GEMM2 =================
__global__ __launch_bounds__(256) void k_gather1(const float* __restrict__ b1,
                                                 const float* __restrict__ W2,
                                                 const float* __restrict__ as2,
                                                 const float* __restrict__ ad2) {
    __shared__ int    s_src[8][32];
    __shared__ float2 s_ee[8][2][32];
    int wIn = threadIdx.x >> 5;
    int lane = threadIdx.x & 31;
    int n = blockIdx.x * 8 + wIn;
    if (n >= NN) return;

    int s = g_start[n], eend = g_start[n + 1];

    // self-loop attention (analytic)
    float4 asn = *(const float4*)&g_asrc1[n * 4];
    float4 adn = *(const float4*)&g_adst1[n * 4];
    float sa0 = asn.x + adn.x; sa0 = sa0 > 0.f ? sa0 : 0.2f * sa0;
    float sa1 = asn.y + adn.y; sa1 = sa1 > 0.f ? sa1 : 0.2f * sa1;
    float sa2 = asn.z + adn.z; sa2 = sa2 > 0.f ? sa2 : 0.2f * sa2;
    float sa3 = asn.w + adn.w; sa3 = sa3 > 0.f ? sa3 : 0.2f * sa3;
    float se0 = __expf(sa0), se1 = __expf(sa1), se2 = __expf(sa2), se3 = __expf(sa3);
    float seA = (lane < 16) ? se0 : se1;
    float seB = (lane < 16) ? se2 : se3;

    float2 fself = __half22float2(g_h1h[(size_t)n * 32 + lane]);
    float acc0 = fself.x * seA;
    float acc1 = fself.y * seB;
    float d0 = 0.f, d1 = 0.f, d2 = 0.f, d3 = 0.f;

    const float2* ep = s_ee[wIn][lane >= 16 ? 1 : 0];

    for (int base = s; base < eend; base += 32) {
        int j = base + lane;
        bool v = (j < eend);
        int sj = v ? g_esrc[j] : 0;
        float4 ev = v ? g_ee[j] : make_float4(0.f, 0.f, 0.f, 0.f);
        d0 += ev.x; d1 += ev.y; d2 += ev.z; d3 += ev.w;
        s_src[wIn][lane] = sj;
        s_ee[wIn][0][lane] = make_float2(ev.x, ev.z);   // heads (0,2)
        s_ee[wIn][1][lane] = make_float2(ev.y, ev.w);   // heads (1,3)
        __syncwarp();

        int cnt = eend - base; if (cnt > 32) cnt = 32;
        int q = 0;
        for (; q + 8 <= cnt; q += 8) {
            unsigned hv[8];
#pragma unroll
            for (int u = 0; u < 8; u++) {
                int sq = s_src[wIn][q + u];
                hv[u] = *(const unsigned*)&g_h1h[(size_t)sq * 32 + lane];
            }
#pragma unroll
            for (int u = 0; u < 8; u++) {
                float2 f = __half22float2(*(__half2*)&hv[u]);
                float2 eq = ep[q + u];
                acc0 = fmaf(f.x, eq.x, acc0);
                acc1 = fmaf(f.y, eq.y, acc1);
            }
        }
        for (; q < cnt; q++) {
            int sq = s_src[wIn][q];
            float2 f = __half22float2(g_h1h[(size_t)sq * 32 + lane]);
            float2 eq = ep[q];
            acc0 = fmaf(f.x, eq.x, acc0);
            acc1 = fmaf(f.y, eq.y, acc1);
        }
        __syncwarp();
    }

#pragma unroll
    for (int off = 16; off; off >>= 1) {
        d0 += __shfl_xor_sync(FULLM, d0, off);
        d1 += __shfl_xor_sync(FULLM, d1, off);
        d2 += __shfl_xor_sync(FULLM, d2, off);
        d3 += __shfl_xor_sync(FULLM, d3, off);
    }
    float dA = ((lane < 16) ? d0 : d1) + seA;
    float dB = ((lane < 16) ? d2 : d3) + seB;

    float o0 = acc0 / (dA + 1e-16f) + b1[lane];
    float o1 = acc1 / (dB + 1e-16f) + b1[lane + 32];
    o0 = o0 > 0.f ? o0 : expm1f(o0);   // ELU
    o1 = o1 > 0.f ? o1 : expm1f(o1);

    float p = o0 * W2[lane] + o1 * W2[lane + 32];
#pragma unroll
    for (int off = 16; off; off >>= 1) p += __shfl_xor_sync(FULLM, p, off);

    if (lane == 0) {
        g_p2[n] = make_float2(p, p * as2[0]);   // {h2, asrc2}
        g_adst2[n] = p * ad2[0];
    }
}

// ================= K5: layer-2 gather + output (self-loop analytic) =================
__global__ __launch_bounds__(256) void k_gather2(float* __restrict__ out,
                                                 const float* __restrict__ b2) {
    int n = (blockIdx.x * 256 + threadIdx.x) >> 5;
    int lane = threadIdx.x & 31;
    if (n >= NN) return;

    int s = g_start[n], eend = g_start[n + 1];
    float adn = g_adst2[n];
    float2 pn = g_p2[n];
    float num = 0.f, den = 0.f;
    for (int j = s + lane; j < eend; j += 32) {
        int src = g_esrc[j];
        float2 hs = g_p2[src];
        float a = hs.y + adn;
        a = a > 0.f ? a : 0.2f * a;
        float e = __expf(a);
        den += e;
        num = fmaf(hs.x, e, num);
    }
#pragma unroll
    for (int off = 16; off; off >>= 1) {
        num += __shfl_xor_sync(FULLM, num, off);
        den += __shfl_xor_sync(FULLM, den, off);
    }
    if (lane == 0) {
        float a = pn.y + adn;
        a = a > 0.f ? a : 0.2f * a;
        float e = __expf(a);
        den += e;
        num = fmaf(pn.x, e, num);
        out[n] = num / (den + 1e-16f) + b2[0];
    }
}

// ---------------- launch ----------------
extern "C" void kernel_launch(void* const* d_in, const int* in_sizes, int n_in,
                              void* d_out, int out_size) {
    const float* x   = (const float*)d_in[0];
    const int*   ei  = (const int*)d_in[1];
    const float* W1  = (const float*)d_in[2];
    const float* as1 = (const float*)d_in[3];
    const float* ad1 = (const float*)d_in[4];
    const float* b1  = (const float*)d_in[5];
    const float* W2  = (const float*)d_in[6];
    const float* as2 = (const float*)d_in[7];
    const float* ad2 = (const float*)d_in[8];
    const float* b2  = (const float*)d_in[9];
    float* out = (float*)d_out;

    k_gemm_hist<<<GEMM_BLOCKS + HIST_BLOCKS, 256>>>(x, W1, as1, ad1, ei);
    k_scan_lb  <<<NBLK, 256>>>();
    k_scatter  <<<(EE / 4 + 255) / 256, 256>>>(ei);
    k_gather1  <<<(NN + 7) / 8, 256>>>(b1, W2, as2, ad2);
    k_gather2  <<<(NN * 32 + 255) / 256, 256>>>(out, b2);
}